// round 1
// baseline (speedup 1.0000x reference)
#include <cuda_runtime.h>

// ---------------------------------------------------------------------------
// LGNN GINE layer, algebraically collapsed:
//   lgX  = 0.5*(x[col0]+x[col1])                          [E,128]
//   2x:  S[v]   = sum_{i: col1[i]==v, col0[i]!=col1[i]} relu(lgX[i]+x[v])
//        lgX    = relu((lgX + S[col0]) @ W1 + b1) @ W2 + b2
//   out  = x + relu( segment_mean(lgX, col1) )
// lg_src / lg_dst / edge_attr_idx inputs are provably redundant.
// ---------------------------------------------------------------------------

#define DD   128
#define DV   32            // float4 per feature row
#define MAXE 200000
#define MAXN 50000

__device__ float g_S[(size_t)MAXN * DD];     // 25.6 MB scratch (node accumulator)
__device__ float g_lgX[(size_t)MAXE * DD];   // 102.4 MB line-node features
__device__ float g_cnt[MAXN];                // per-node edge counts

// --------------------------- init: lgX = 0.5*(x[c0]+x[c1]) ------------------
__global__ void k_init(const float* __restrict__ x,
                       const int* __restrict__ col0,
                       const int* __restrict__ col1, int E)
{
    int idx = blockIdx.x * blockDim.x + threadIdx.x;
    int e = idx >> 5, q = idx & 31;
    if (e >= E) return;
    const float4* x4 = (const float4*)x;
    float4 a = x4[(size_t)col0[e] * DV + q];
    float4 b = x4[(size_t)col1[e] * DV + q];
    float4 r;
    r.x = 0.5f * (a.x + b.x);
    r.y = 0.5f * (a.y + b.y);
    r.z = 0.5f * (a.z + b.z);
    r.w = 0.5f * (a.w + b.w);
    ((float4*)g_lgX)[(size_t)e * DV + q] = r;
}

__device__ __forceinline__ void red_add_v4(float* p, float4 v)
{
    asm volatile("red.global.add.v4.f32 [%0], {%1,%2,%3,%4};"
                 :: "l"(p), "f"(v.x), "f"(v.y), "f"(v.z), "f"(v.w)
                 : "memory");
}

// ------------------- message scatter: S[col1] += relu(lgX + x[col1]) --------
__global__ void k_msg(const float* __restrict__ x,
                      const int* __restrict__ col0,
                      const int* __restrict__ col1, int E)
{
    int idx = blockIdx.x * blockDim.x + threadIdx.x;
    int e = idx >> 5, q = idx & 31;
    if (e >= E) return;
    int c1 = col1[e];
    if (col0[e] == c1) return;               // self-loop edges emit no messages
    float4 a = ((const float4*)g_lgX)[(size_t)e * DV + q];
    float4 xs = ((const float4*)x)[(size_t)c1 * DV + q];
    float4 v;
    v.x = fmaxf(a.x + xs.x, 0.f);
    v.y = fmaxf(a.y + xs.y, 0.f);
    v.z = fmaxf(a.z + xs.z, 0.f);
    v.w = fmaxf(a.w + xs.w, 0.f);
    red_add_v4(&g_S[(size_t)c1 * DD + 4 * q], v);
}

// --------------- fused MLP: lgX = relu((lgX+S[col0])@W1+b1)@W2+b2 -----------
// One block = 128 rows. smem: A tile [128][132] (padded) + W buffer [128][128].
#define LDA 132
#define SMEM_BYTES ((128 * LDA + 128 * 128) * 4)

__global__ void __launch_bounds__(256, 1)
k_mlp(const int* __restrict__ col0,
      const float* __restrict__ W1, const float* __restrict__ b1,
      const float* __restrict__ W2, const float* __restrict__ b2,
      int E)
{
    extern __shared__ float sm[];
    float* sA = sm;                   // [128][LDA]
    float* sW = sm + 128 * LDA;       // [128][128], holds W1 then W2

    const int tid  = threadIdx.x;
    const int row0 = blockIdx.x * 128;

    // stage W1
    {
        const float4* w4 = (const float4*)W1;
        float4* s4 = (float4*)sW;
        #pragma unroll
        for (int i = tid; i < 4096; i += 256) s4[i] = w4[i];
    }
    // stage A = lgX + S[col0]  (gather fused into tile load)
    #pragma unroll
    for (int i = tid; i < 4096; i += 256) {
        int r = i >> 5, q = i & 31;
        int gr = row0 + r;
        float4 v = make_float4(0.f, 0.f, 0.f, 0.f);
        if (gr < E) {
            float4 a = ((const float4*)g_lgX)[(size_t)gr * DV + q];
            int c = col0[gr];
            float4 s = ((const float4*)g_S)[(size_t)c * DV + q];
            v.x = a.x + s.x; v.y = a.y + s.y; v.z = a.z + s.z; v.w = a.w + s.w;
        }
        *(float4*)&sA[r * LDA + 4 * q] = v;
    }
    __syncthreads();

    const int tx = tid & 15, ty = tid >> 4;
    const int r0 = ty * 8, c0 = tx * 8;

    float acc[8][8];
    #pragma unroll
    for (int i = 0; i < 8; i++)
        #pragma unroll
        for (int j = 0; j < 8; j++) acc[i][j] = 0.f;

    // GEMM 1: acc = A @ W1
    #pragma unroll 4
    for (int k = 0; k < 128; k++) {
        float a[8], b[8];
        #pragma unroll
        for (int i = 0; i < 8; i++) a[i] = sA[(r0 + i) * LDA + k];
        *(float4*)&b[0] = *(float4*)&sW[k * 128 + c0];
        *(float4*)&b[4] = *(float4*)&sW[k * 128 + c0 + 4];
        #pragma unroll
        for (int i = 0; i < 8; i++)
            #pragma unroll
            for (int j = 0; j < 8; j++)
                acc[i][j] = fmaf(a[i], b[j], acc[i][j]);
    }
    __syncthreads();   // all reads of sA/sW done

    // T = relu(acc + b1) -> sA ; stage W2 -> sW
    {
        float bb[8];
        #pragma unroll
        for (int j = 0; j < 8; j++) bb[j] = b1[c0 + j];
        #pragma unroll
        for (int i = 0; i < 8; i++) {
            float4 t0, t1;
            t0.x = fmaxf(acc[i][0] + bb[0], 0.f);
            t0.y = fmaxf(acc[i][1] + bb[1], 0.f);
            t0.z = fmaxf(acc[i][2] + bb[2], 0.f);
            t0.w = fmaxf(acc[i][3] + bb[3], 0.f);
            t1.x = fmaxf(acc[i][4] + bb[4], 0.f);
            t1.y = fmaxf(acc[i][5] + bb[5], 0.f);
            t1.z = fmaxf(acc[i][6] + bb[6], 0.f);
            t1.w = fmaxf(acc[i][7] + bb[7], 0.f);
            *(float4*)&sA[(r0 + i) * LDA + c0]     = t0;
            *(float4*)&sA[(r0 + i) * LDA + c0 + 4] = t1;
        }
        const float4* w4 = (const float4*)W2;
        float4* s4 = (float4*)sW;
        #pragma unroll
        for (int i = tid; i < 4096; i += 256) s4[i] = w4[i];
    }
    __syncthreads();

    #pragma unroll
    for (int i = 0; i < 8; i++)
        #pragma unroll
        for (int j = 0; j < 8; j++) acc[i][j] = 0.f;

    // GEMM 2: acc = T @ W2
    #pragma unroll 4
    for (int k = 0; k < 128; k++) {
        float a[8], b[8];
        #pragma unroll
        for (int i = 0; i < 8; i++) a[i] = sA[(r0 + i) * LDA + k];
        *(float4*)&b[0] = *(float4*)&sW[k * 128 + c0];
        *(float4*)&b[4] = *(float4*)&sW[k * 128 + c0 + 4];
        #pragma unroll
        for (int i = 0; i < 8; i++)
            #pragma unroll
            for (int j = 0; j < 8; j++)
                acc[i][j] = fmaf(a[i], b[j], acc[i][j]);
    }

    // write lgX = acc + b2 (no relu on second layer)
    {
        float bb[8];
        #pragma unroll
        for (int j = 0; j < 8; j++) bb[j] = b2[c0 + j];
        #pragma unroll
        for (int i = 0; i < 8; i++) {
            int gr = row0 + r0 + i;
            if (gr < E) {
                float4 o0, o1;
                o0.x = acc[i][0] + bb[0];
                o0.y = acc[i][1] + bb[1];
                o0.z = acc[i][2] + bb[2];
                o0.w = acc[i][3] + bb[3];
                o1.x = acc[i][4] + bb[4];
                o1.y = acc[i][5] + bb[5];
                o1.z = acc[i][6] + bb[6];
                o1.w = acc[i][7] + bb[7];
                *(float4*)&g_lgX[(size_t)gr * DD + c0]     = o0;
                *(float4*)&g_lgX[(size_t)gr * DD + c0 + 4] = o1;
            }
        }
    }
}

// ---------------- final scatter: S[col1] += lgX ; cnt[col1] += 1 ------------
__global__ void k_fscatter(const int* __restrict__ col1, int E)
{
    int idx = blockIdx.x * blockDim.x + threadIdx.x;
    int e = idx >> 5, q = idx & 31;
    if (e >= E) return;
    int c1 = col1[e];
    float4 v = ((const float4*)g_lgX)[(size_t)e * DV + q];
    red_add_v4(&g_S[(size_t)c1 * DD + 4 * q], v);
    if (q == 0) atomicAdd(&g_cnt[c1], 1.0f);
}

// ----------------------- out = x + relu(mean or 0) --------------------------
__global__ void k_fout(const float* __restrict__ x, float* __restrict__ out, int N)
{
    int idx = blockIdx.x * blockDim.x + threadIdx.x;
    int v = idx >> 5, q = idx & 31;
    if (v >= N) return;
    float c   = g_cnt[v];
    float inv = (c > 0.f) ? (1.f / c) : 0.f;
    float4 s  = ((const float4*)g_S)[(size_t)v * DV + q];
    float4 xv = ((const float4*)x)[(size_t)v * DV + q];
    float4 o;
    o.x = xv.x + fmaxf(s.x * inv, 0.f);
    o.y = xv.y + fmaxf(s.y * inv, 0.f);
    o.z = xv.z + fmaxf(s.z * inv, 0.f);
    o.w = xv.w + fmaxf(s.w * inv, 0.f);
    ((float4*)out)[(size_t)v * DV + q] = o;
}

// ---------------------------------------------------------------------------
extern "C" void kernel_launch(void* const* d_in, const int* in_sizes, int n_in,
                              void* d_out, int out_size)
{
    const float* x   = (const float*)d_in[0];
    const float* W1  = (const float*)d_in[1];
    const float* b1  = (const float*)d_in[2];
    const float* W2  = (const float*)d_in[3];
    const float* b2  = (const float*)d_in[4];
    const int*   col0 = (const int*)d_in[5];
    const int*   col1 = (const int*)d_in[6];
    // d_in[7..9] (lg_src, lg_dst, edge_attr_idx) are algebraically redundant.

    const int E = in_sizes[5];
    const int N = in_sizes[0] / DD;
    float* out = (float*)d_out;

    void* pS;  cudaGetSymbolAddress(&pS, g_S);
    void* pC;  cudaGetSymbolAddress(&pC, g_cnt);

    cudaFuncSetAttribute((const void*)k_mlp,
                         cudaFuncAttributeMaxDynamicSharedMemorySize, SMEM_BYTES);

    const int tpb = 256;
    const int nbE = (E * 32 + tpb - 1) / tpb;   // one thread per (edge, float4)
    const int nbN = (N * 32 + tpb - 1) / tpb;
    const int nbM = (E + 127) / 128;

    cudaMemsetAsync(pS, 0, (size_t)N * DD * sizeof(float));
    k_init<<<nbE, tpb>>>(x, col0, col1, E);

    for (int it = 0; it < 2; it++) {
        if (it) cudaMemsetAsync(pS, 0, (size_t)N * DD * sizeof(float));
        k_msg<<<nbE, tpb>>>(x, col0, col1, E);
        k_mlp<<<nbM, 256, SMEM_BYTES>>>(col0, W1, b1, W2, b2, E);
    }

    cudaMemsetAsync(pS, 0, (size_t)N * DD * sizeof(float));
    cudaMemsetAsync(pC, 0, (size_t)N * sizeof(float));
    k_fscatter<<<nbE, tpb>>>(col1, E);
    k_fout<<<nbN, tpb>>>(x, out, N);
}

// round 3
// speedup vs baseline: 1.4759x; 1.4759x over previous
#include <cuda_runtime.h>
#include <cstdint>

// ---------------------------------------------------------------------------
// LGNN GINE layer, algebraically collapsed + tf32 mma.sync MLP.
//   lgX  = 0.5*(x[col0]+x[col1])
//   2x:  S[v] = sum_{i: col1[i]==v, col0[i]!=col1[i]} relu(lgX[i]+x[v])
//        lgX  = relu((lgX + S[col0]) @ W1 + b1) @ W2 + b2
//   out  = x + relu( segment_mean(lgX, col1) )
// Next-iteration message scatter fused into the MLP epilogue (messages depend
// only on the source line-node), ping-ponging S buffers. Final iteration
// scatters directly to Sf and never writes lgX back to DRAM.
// ---------------------------------------------------------------------------

#define DD   128
#define DV   32
#define MAXE 200000
#define MAXN 50000

__device__ float g_S0[(size_t)MAXN * DD];
__device__ float g_S1[(size_t)MAXN * DD];
__device__ float g_Sf[(size_t)MAXN * DD];
__device__ float g_lgX[(size_t)MAXE * DD];
__device__ float g_cnt[MAXN];
__device__ float g_Wr1[DD * DD];   // W1, tf32-rounded, [k][n]
__device__ float g_Wr2[DD * DD];

// ----------------------------- helpers --------------------------------------
__device__ __forceinline__ float tf32r(float f) {
    uint32_t u;
    asm("cvt.rna.tf32.f32 %0, %1;" : "=r"(u) : "f"(f));
    return __uint_as_float(u);
}
__device__ __forceinline__ void red_add_v4(float* p, float4 v) {
    asm volatile("red.global.add.v4.f32 [%0], {%1,%2,%3,%4};"
                 :: "l"(p), "f"(v.x), "f"(v.y), "f"(v.z), "f"(v.w) : "memory");
}
__device__ __forceinline__ void red_add_v2(float* p, float2 v) {
    asm volatile("red.global.add.v2.f32 [%0], {%1,%2};"
                 :: "l"(p), "f"(v.x), "f"(v.y) : "memory");
}
__device__ __forceinline__ void mma_tf32(float* d, const uint32_t* a,
                                         const uint32_t* b) {
    asm volatile(
        "mma.sync.aligned.m16n8k8.row.col.f32.tf32.tf32.f32 "
        "{%0,%1,%2,%3}, {%4,%5,%6,%7}, {%8,%9}, {%0,%1,%2,%3};"
        : "+f"(d[0]), "+f"(d[1]), "+f"(d[2]), "+f"(d[3])
        : "r"(a[0]), "r"(a[1]), "r"(a[2]), "r"(a[3]), "r"(b[0]), "r"(b[1]));
}

// ------------------- weight tf32 rounding (once) ----------------------------
__global__ void k_wt(const float* __restrict__ W1, const float* __restrict__ W2)
{
    int t = blockIdx.x * blockDim.x + threadIdx.x;
    if (t >= DD * DD) return;
    g_Wr1[t] = tf32r(W1[t]);
    g_Wr2[t] = tf32r(W2[t]);
}

// ---- init: lgX = 0.5*(x[c0]+x[c1]); scatter relu(lgX+x[c1]) -> S0; cnt -----
__global__ void k_init(const float* __restrict__ x,
                       const int* __restrict__ col0,
                       const int* __restrict__ col1, int E)
{
    int idx = blockIdx.x * blockDim.x + threadIdx.x;
    int e = idx >> 5, q = idx & 31;
    if (e >= E) return;
    int c0 = col0[e], c1 = col1[e];
    const float4* x4 = (const float4*)x;
    float4 a = x4[(size_t)c0 * DV + q];
    float4 b = x4[(size_t)c1 * DV + q];
    float4 r;
    r.x = 0.5f * (a.x + b.x);
    r.y = 0.5f * (a.y + b.y);
    r.z = 0.5f * (a.z + b.z);
    r.w = 0.5f * (a.w + b.w);
    ((float4*)g_lgX)[(size_t)e * DV + q] = r;
    if (c0 != c1) {
        float4 v;
        v.x = fmaxf(r.x + b.x, 0.f);
        v.y = fmaxf(r.y + b.y, 0.f);
        v.z = fmaxf(r.z + b.z, 0.f);
        v.w = fmaxf(r.w + b.w, 0.f);
        red_add_v4(&g_S0[(size_t)c1 * DD + 4 * q], v);
    }
    if (q == 0) atomicAdd(&g_cnt[c1], 1.0f);
}

// ----------------- fused MLP + next-iteration message scatter ---------------
// 256 threads, 128 rows/CTA. Warp tile 32x64 (2 m16 x 8 n8), K=128 (16 k8).
#define LDA 132            // sA stride (words): conflict-free A-fragment loads
#define LDW 136            // sW stride (words): conflict-free B-fragment loads
#define SMEM_BYTES ((128 * LDA + 2 * 128 * LDW) * 4)   // 206848 B

__global__ void __launch_bounds__(256, 1)
k_mlp(const int* __restrict__ col0, const int* __restrict__ col1,
      const float* __restrict__ x,
      const float* __restrict__ b1, const float* __restrict__ b2,
      const float* __restrict__ Sin, float* __restrict__ Sout,
      int E, int final_mode)
{
    extern __shared__ float sm[];
    float* sA  = sm;                       // [128][LDA]
    float* sW1 = sm + 128 * LDA;           // [128][LDW]
    float* sW2 = sW1 + 128 * LDW;

    const int tid  = threadIdx.x;
    const int wid  = tid >> 5, lane = tid & 31;
    const int ty   = lane >> 2, tx4 = lane & 3;    // fragment row/col sel
    const int wm   = wid >> 1, wn = wid & 1;
    const int r0   = wm * 32;                      // warp row base (in tile)
    const int c0   = wn * 64;                      // warp col base
    const int row0 = blockIdx.x * 128;

    // stage W1/W2 (already tf32-rounded)
    #pragma unroll
    for (int i = tid; i < 4096; i += 256) {
        int k = i >> 5, n4 = i & 31;
        float4 w1 = ((const float4*)g_Wr1)[i];
        float4 w2 = ((const float4*)g_Wr2)[i];
        *(float4*)&sW1[k * LDW + 4 * n4] = w1;
        *(float4*)&sW2[k * LDW + 4 * n4] = w2;
    }
    // stage A = tf32r(lgX[r] + Sin[col0[r]])
    #pragma unroll
    for (int i = tid; i < 4096; i += 256) {
        int r = i >> 5, q = i & 31;
        int gr = row0 + r;
        float4 v = make_float4(0.f, 0.f, 0.f, 0.f);
        if (gr < E) {
            float4 a = ((const float4*)g_lgX)[(size_t)gr * DV + q];
            float4 s = ((const float4*)Sin)[(size_t)col0[gr] * DV + q];
            v.x = tf32r(a.x + s.x); v.y = tf32r(a.y + s.y);
            v.z = tf32r(a.z + s.z); v.w = tf32r(a.w + s.w);
        }
        *(float4*)&sA[r * LDA + 4 * q] = v;
    }
    __syncthreads();

    float acc[2][8][4];
    #pragma unroll
    for (int m = 0; m < 2; m++)
        #pragma unroll
        for (int n = 0; n < 8; n++)
            #pragma unroll
            for (int j = 0; j < 4; j++) acc[m][n][j] = 0.f;

    const uint32_t* uA = (const uint32_t*)sA;

    // ---------------- GEMM 1: acc = A @ W1 ----------------
    {
        const uint32_t* uW = (const uint32_t*)sW1;
        #pragma unroll
        for (int kk = 0; kk < 16; kk++) {
            uint32_t a[2][4], b[8][2];
            #pragma unroll
            for (int m = 0; m < 2; m++) {
                int rb = r0 + 16 * m;
                a[m][0] = uA[(rb + ty) * LDA + kk * 8 + tx4];
                a[m][1] = uA[(rb + ty + 8) * LDA + kk * 8 + tx4];
                a[m][2] = uA[(rb + ty) * LDA + kk * 8 + tx4 + 4];
                a[m][3] = uA[(rb + ty + 8) * LDA + kk * 8 + tx4 + 4];
            }
            #pragma unroll
            for (int n = 0; n < 8; n++) {
                int cc = c0 + 8 * n + ty;
                b[n][0] = uW[(kk * 8 + tx4) * LDW + cc];
                b[n][1] = uW[(kk * 8 + tx4 + 4) * LDW + cc];
            }
            #pragma unroll
            for (int m = 0; m < 2; m++)
                #pragma unroll
                for (int n = 0; n < 8; n++)
                    mma_tf32(acc[m][n], a[m], b[n]);
        }
    }
    __syncthreads();   // all GEMM-1 reads of sA done before T overwrites it

    // epilogue 1: T = tf32r(relu(acc + b1)) -> sA
    #pragma unroll
    for (int m = 0; m < 2; m++) {
        int rb = r0 + 16 * m + ty;
        #pragma unroll
        for (int n = 0; n < 8; n++) {
            int cc = c0 + 8 * n + 2 * tx4;
            float2 bb = *(const float2*)&b1[cc];
            float2 t0, t1;
            t0.x = tf32r(fmaxf(acc[m][n][0] + bb.x, 0.f));
            t0.y = tf32r(fmaxf(acc[m][n][1] + bb.y, 0.f));
            t1.x = tf32r(fmaxf(acc[m][n][2] + bb.x, 0.f));
            t1.y = tf32r(fmaxf(acc[m][n][3] + bb.y, 0.f));
            *(float2*)&sA[rb * LDA + cc]       = t0;
            *(float2*)&sA[(rb + 8) * LDA + cc] = t1;
            acc[m][n][0] = 0.f; acc[m][n][1] = 0.f;
            acc[m][n][2] = 0.f; acc[m][n][3] = 0.f;
        }
    }
    __syncthreads();

    // ---------------- GEMM 2: acc = T @ W2 ----------------
    {
        const uint32_t* uW = (const uint32_t*)sW2;
        #pragma unroll
        for (int kk = 0; kk < 16; kk++) {
            uint32_t a[2][4], b[8][2];
            #pragma unroll
            for (int m = 0; m < 2; m++) {
                int rb = r0 + 16 * m;
                a[m][0] = uA[(rb + ty) * LDA + kk * 8 + tx4];
                a[m][1] = uA[(rb + ty + 8) * LDA + kk * 8 + tx4];
                a[m][2] = uA[(rb + ty) * LDA + kk * 8 + tx4 + 4];
                a[m][3] = uA[(rb + ty + 8) * LDA + kk * 8 + tx4 + 4];
            }
            #pragma unroll
            for (int n = 0; n < 8; n++) {
                int cc = c0 + 8 * n + ty;
                b[n][0] = uW[(kk * 8 + tx4) * LDW + cc];
                b[n][1] = uW[(kk * 8 + tx4 + 4) * LDW + cc];
            }
            #pragma unroll
            for (int m = 0; m < 2; m++)
                #pragma unroll
                for (int n = 0; n < 8; n++)
                    mma_tf32(acc[m][n], a[m], b[n]);
        }
    }

    // epilogue 2: O = acc + b2 ; write lgX (unless final) ; fused scatter
    #pragma unroll
    for (int m = 0; m < 2; m++) {
        #pragma unroll
        for (int half = 0; half < 2; half++) {
            int row = r0 + 16 * m + ty + 8 * half;
            int gr  = row0 + row;
            if (gr >= E) continue;
            int c1 = col1[gr];
            bool emit = true;
            if (!final_mode) emit = (col0[gr] != c1);
            #pragma unroll
            for (int n = 0; n < 8; n++) {
                int cc = c0 + 8 * n + 2 * tx4;
                float2 bb = *(const float2*)&b2[cc];
                float2 o;
                o.x = acc[m][n][2 * half + 0] + bb.x;
                o.y = acc[m][n][2 * half + 1] + bb.y;
                if (!final_mode) {
                    *(float2*)&g_lgX[(size_t)gr * DD + cc] = o;
                    if (emit) {
                        float2 xs = *(const float2*)&x[(size_t)c1 * DD + cc];
                        float2 v;
                        v.x = fmaxf(o.x + xs.x, 0.f);
                        v.y = fmaxf(o.y + xs.y, 0.f);
                        red_add_v2(&Sout[(size_t)c1 * DD + cc], v);
                    }
                } else {
                    red_add_v2(&Sout[(size_t)c1 * DD + cc], o);
                }
            }
        }
    }
}

// ----------------------- out = x + relu(Sf/cnt or 0) ------------------------
__global__ void k_fout(const float* __restrict__ x, float* __restrict__ out, int N)
{
    int idx = blockIdx.x * blockDim.x + threadIdx.x;
    int v = idx >> 5, q = idx & 31;
    if (v >= N) return;
    float c   = g_cnt[v];
    float inv = (c > 0.f) ? (1.f / c) : 0.f;
    float4 s  = ((const float4*)g_Sf)[(size_t)v * DV + q];
    float4 xv = ((const float4*)x)[(size_t)v * DV + q];
    float4 o;
    o.x = xv.x + fmaxf(s.x * inv, 0.f);
    o.y = xv.y + fmaxf(s.y * inv, 0.f);
    o.z = xv.z + fmaxf(s.z * inv, 0.f);
    o.w = xv.w + fmaxf(s.w * inv, 0.f);
    ((float4*)out)[(size_t)v * DV + q] = o;
}

// ---------------------------------------------------------------------------
extern "C" void kernel_launch(void* const* d_in, const int* in_sizes, int n_in,
                              void* d_out, int out_size)
{
    const float* x    = (const float*)d_in[0];
    const float* W1   = (const float*)d_in[1];
    const float* b1   = (const float*)d_in[2];
    const float* W2   = (const float*)d_in[3];
    const float* b2   = (const float*)d_in[4];
    const int*   col0 = (const int*)d_in[5];
    const int*   col1 = (const int*)d_in[6];
    // lg_src / lg_dst / edge_attr_idx are algebraically redundant.

    const int E = in_sizes[5];
    const int N = in_sizes[0] / DD;
    float* out = (float*)d_out;

    void *pS0, *pS1, *pSf, *pC;
    cudaGetSymbolAddress(&pS0, g_S0);
    cudaGetSymbolAddress(&pS1, g_S1);
    cudaGetSymbolAddress(&pSf, g_Sf);
    cudaGetSymbolAddress(&pC,  g_cnt);

    cudaFuncSetAttribute((const void*)k_mlp,
                         cudaFuncAttributeMaxDynamicSharedMemorySize, SMEM_BYTES);

    const int tpb = 256;
    const int nbE = (E * 32 + tpb - 1) / tpb;
    const int nbN = (N * 32 + tpb - 1) / tpb;
    const int nbM = (E + 127) / 128;

    cudaMemsetAsync(pS0, 0, (size_t)N * DD * sizeof(float));
    cudaMemsetAsync(pS1, 0, (size_t)N * DD * sizeof(float));
    cudaMemsetAsync(pSf, 0, (size_t)N * DD * sizeof(float));
    cudaMemsetAsync(pC,  0, (size_t)N * sizeof(float));

    k_wt<<<(DD * DD + tpb - 1) / tpb, tpb>>>(W1, W2);
    k_init<<<nbE, tpb>>>(x, col0, col1, E);
    k_mlp<<<nbM, tpb, SMEM_BYTES>>>(col0, col1, x, b1, b2,
                                    (const float*)pS0, (float*)pS1, E, 0);
    k_mlp<<<nbM, tpb, SMEM_BYTES>>>(col0, col1, x, b1, b2,
                                    (const float*)pS1, (float*)pSf, E, 1);
    k_fout<<<nbN, tpb>>>(x, out, N);
}

// round 4
// speedup vs baseline: 1.6308x; 1.1050x over previous
#include <cuda_runtime.h>
#include <cstdint>

// ---------------------------------------------------------------------------
// LGNN GINE layer, algebraically collapsed + persistent two-team tf32 MMA MLP.
//   lgX  = 0.5*(x[col0]+x[col1])
//   2x:  S[v] = sum_{i: col1[i]==v, col0[i]!=col1[i]} relu(lgX[i]+x[v])
//        lgX  = relu((lgX + S[col0]) @ W1 + b1) @ W2 + b2
//   out  = x + relu( segment_mean(lgX, col1) )
// Next-iteration message scatter fused into the MLP epilogue; S ping-pong.
// k_mlp is persistent: W staged once per CTA; 8 warps = 2 independent teams
// of 4, each streaming 64-row tiles; only pairwise named barriers inside.
// ---------------------------------------------------------------------------

#define DD   128
#define DV   32
#define MAXE 200000
#define MAXN 50000
#define TILE 64

__device__ float g_S0[(size_t)MAXN * DD];
__device__ float g_S1[(size_t)MAXN * DD];
__device__ float g_Sf[(size_t)MAXN * DD];
__device__ float g_lgX[(size_t)MAXE * DD];
__device__ float g_cnt[MAXN];
__device__ float g_Wr1[DD * DD];   // W1, tf32-rounded, [k][n]
__device__ float g_Wr2[DD * DD];

// ----------------------------- helpers --------------------------------------
__device__ __forceinline__ float tf32r(float f) {
    uint32_t u;
    asm("cvt.rna.tf32.f32 %0, %1;" : "=r"(u) : "f"(f));
    return __uint_as_float(u);
}
__device__ __forceinline__ void red_add_v4(float* p, float4 v) {
    asm volatile("red.global.add.v4.f32 [%0], {%1,%2,%3,%4};"
                 :: "l"(p), "f"(v.x), "f"(v.y), "f"(v.z), "f"(v.w) : "memory");
}
__device__ __forceinline__ void red_add_v2(float* p, float2 v) {
    asm volatile("red.global.add.v2.f32 [%0], {%1,%2};"
                 :: "l"(p), "f"(v.x), "f"(v.y) : "memory");
}
__device__ __forceinline__ void mma_tf32(float* d, const uint32_t* a,
                                         const uint32_t* b) {
    asm volatile(
        "mma.sync.aligned.m16n8k8.row.col.f32.tf32.tf32.f32 "
        "{%0,%1,%2,%3}, {%4,%5,%6,%7}, {%8,%9}, {%0,%1,%2,%3};"
        : "+f"(d[0]), "+f"(d[1]), "+f"(d[2]), "+f"(d[3])
        : "r"(a[0]), "r"(a[1]), "r"(a[2]), "r"(a[3]), "r"(b[0]), "r"(b[1]));
}
#define BAR(id) asm volatile("bar.sync %0, 64;" :: "r"(id) : "memory")

// ------------------- zero scratch + weight rounding --------------------------
__global__ void k_zero(float4* s0, float4* s1, float4* sf, float* cnt, int n4, int n)
{
    int i = blockIdx.x * blockDim.x + threadIdx.x;
    float4 z = make_float4(0.f, 0.f, 0.f, 0.f);
    if (i < n4) { s0[i] = z; s1[i] = z; sf[i] = z; }
    if (i < n)  cnt[i] = 0.f;
}
__global__ void k_wt(const float* __restrict__ W1, const float* __restrict__ W2)
{
    int t = blockIdx.x * blockDim.x + threadIdx.x;
    if (t >= DD * DD) return;
    g_Wr1[t] = tf32r(W1[t]);
    g_Wr2[t] = tf32r(W2[t]);
}

// ---- init: lgX = 0.5*(x[c0]+x[c1]); scatter relu(lgX+x[c1]) -> S0; cnt -----
__global__ void k_init(const float* __restrict__ x,
                       const int* __restrict__ col0,
                       const int* __restrict__ col1, int E)
{
    int idx = blockIdx.x * blockDim.x + threadIdx.x;
    int e = idx >> 5, q = idx & 31;
    if (e >= E) return;
    int c0 = col0[e], c1 = col1[e];
    const float4* x4 = (const float4*)x;
    float4 a = x4[(size_t)c0 * DV + q];
    float4 b = x4[(size_t)c1 * DV + q];
    float4 r;
    r.x = 0.5f * (a.x + b.x);
    r.y = 0.5f * (a.y + b.y);
    r.z = 0.5f * (a.z + b.z);
    r.w = 0.5f * (a.w + b.w);
    ((float4*)g_lgX)[(size_t)e * DV + q] = r;
    if (c0 != c1) {
        float4 v;
        v.x = fmaxf(r.x + b.x, 0.f);
        v.y = fmaxf(r.y + b.y, 0.f);
        v.z = fmaxf(r.z + b.z, 0.f);
        v.w = fmaxf(r.w + b.w, 0.f);
        red_add_v4(&g_S0[(size_t)c1 * DD + 4 * q], v);
    }
    if (q == 0) atomicAdd(&g_cnt[c1], 1.0f);
}

// ----------------- persistent fused MLP + message scatter -------------------
#define LDA 132
#define LDW 136
#define SW_WORDS (128 * LDW)
#define SA_WORDS (TILE * LDA)
#define SMEM_BYTES ((2 * SW_WORDS + 2 * SA_WORDS) * 4)   // 206848 B

#define GEMM_BODY(UW)                                                          \
    _Pragma("unroll")                                                          \
    for (int kk = 0; kk < 16; kk++) {                                          \
        uint32_t a[2][4], b[8][2];                                             \
        _Pragma("unroll")                                                      \
        for (int m = 0; m < 2; m++) {                                          \
            int rb = R0 + 16 * m;                                              \
            a[m][0] = uA[(rb + ty) * LDA + kk * 8 + tx4];                      \
            a[m][1] = uA[(rb + ty + 8) * LDA + kk * 8 + tx4];                  \
            a[m][2] = uA[(rb + ty) * LDA + kk * 8 + tx4 + 4];                  \
            a[m][3] = uA[(rb + ty + 8) * LDA + kk * 8 + tx4 + 4];              \
        }                                                                      \
        _Pragma("unroll")                                                      \
        for (int n = 0; n < 8; n++) {                                          \
            int cc = wn * 64 + 8 * n + ty;                                     \
            b[n][0] = (UW)[(kk * 8 + tx4) * LDW + cc];                         \
            b[n][1] = (UW)[(kk * 8 + tx4 + 4) * LDW + cc];                     \
        }                                                                      \
        _Pragma("unroll")                                                      \
        for (int m = 0; m < 2; m++)                                            \
            _Pragma("unroll")                                                  \
            for (int n = 0; n < 8; n++)                                        \
                mma_tf32(acc[m][n], a[m], b[n]);                               \
    }

__global__ void __launch_bounds__(256, 1)
k_mlp(const int* __restrict__ col0, const int* __restrict__ col1,
      const float* __restrict__ x,
      const float* __restrict__ b1, const float* __restrict__ b2,
      const float* __restrict__ Sin, float* __restrict__ Sout,
      int E, int final_mode, int ntiles, int tstride)
{
    extern __shared__ float sm[];
    float* sW1 = sm;
    float* sW2 = sm + SW_WORDS;

    const int tid  = threadIdx.x;
    const int wid  = tid >> 5, lane = tid & 31;
    const int team = wid >> 2;                 // 0 / 1
    const int twid = wid & 3;
    const int wm   = twid >> 1, wn = twid & 1; // row-pair / col-half in team
    const int ty   = lane >> 2, tx4 = lane & 3;
    const int R0   = wm * 32;                  // local row base (within 64)
    const int barid = 1 + (wid >> 1);          // pair barrier id (1..4)

    float* sA = sm + 2 * SW_WORDS + team * SA_WORDS;
    const uint32_t* uA  = (const uint32_t*)sA;
    const uint32_t* uW1 = (const uint32_t*)sW1;
    const uint32_t* uW2 = (const uint32_t*)sW2;

    // stage weights once
    #pragma unroll
    for (int i = tid; i < 4096; i += 256) {
        int k = i >> 5, n4 = i & 31;
        *(float4*)&sW1[k * LDW + 4 * n4] = ((const float4*)g_Wr1)[i];
        *(float4*)&sW2[k * LDW + 4 * n4] = ((const float4*)g_Wr2)[i];
    }
    __syncthreads();

    const float4* lgX4 = (const float4*)g_lgX;
    const float4* Sin4 = (const float4*)Sin;
    const int w0   = wn * 16;
    const int rsel = lane >> 4;       // 0/1: row within stage pair
    const int wsel = lane & 15;       // word within 64-col half

    for (int tile = blockIdx.x * 2 + team; tile < ntiles; tile += tstride) {
        const int row0 = tile * TILE;

        // ---- stage A = tf32r(lgX[r] + Sin[col0[r]]) : own 32 rows, 64 cols
        #pragma unroll
        for (int j = 0; j < 16; j++) {
            int rloc = 2 * j + rsel;
            int gr = row0 + R0 + rloc;
            float4 v = make_float4(0.f, 0.f, 0.f, 0.f);
            if (gr < E) {
                float4 a = lgX4[(size_t)gr * DV + w0 + wsel];
                int c = col0[gr];
                float4 s = Sin4[(size_t)c * DV + w0 + wsel];
                v.x = tf32r(a.x + s.x); v.y = tf32r(a.y + s.y);
                v.z = tf32r(a.z + s.z); v.w = tf32r(a.w + s.w);
            }
            *(float4*)&sA[(R0 + rloc) * LDA + 4 * (w0 + wsel)] = v;
        }
        BAR(barid);

        float acc[2][8][4];
        #pragma unroll
        for (int m = 0; m < 2; m++)
            #pragma unroll
            for (int n = 0; n < 8; n++)
                #pragma unroll
                for (int j = 0; j < 4; j++) acc[m][n][j] = 0.f;

        // ---------------- GEMM 1: acc = A @ W1 ----------------
        GEMM_BODY(uW1);
        BAR(barid);

        // epilogue 1: T = tf32r(relu(acc + b1)) -> sA (in place)
        #pragma unroll
        for (int m = 0; m < 2; m++) {
            int rb = R0 + 16 * m + ty;
            #pragma unroll
            for (int n = 0; n < 8; n++) {
                int cc = wn * 64 + 8 * n + 2 * tx4;
                float2 bb = *(const float2*)&b1[cc];
                float2 t0, t1;
                t0.x = tf32r(fmaxf(acc[m][n][0] + bb.x, 0.f));
                t0.y = tf32r(fmaxf(acc[m][n][1] + bb.y, 0.f));
                t1.x = tf32r(fmaxf(acc[m][n][2] + bb.x, 0.f));
                t1.y = tf32r(fmaxf(acc[m][n][3] + bb.y, 0.f));
                *(float2*)&sA[rb * LDA + cc]       = t0;
                *(float2*)&sA[(rb + 8) * LDA + cc] = t1;
                acc[m][n][0] = 0.f; acc[m][n][1] = 0.f;
                acc[m][n][2] = 0.f; acc[m][n][3] = 0.f;
            }
        }
        BAR(barid);

        // ---------------- GEMM 2: acc = T @ W2 ----------------
        GEMM_BODY(uW2);

        // epilogue 2: O = acc + b2 ; write lgX (unless final); fused scatter
        #pragma unroll
        for (int m = 0; m < 2; m++) {
            #pragma unroll
            for (int half = 0; half < 2; half++) {
                int gr = row0 + R0 + 16 * m + ty + 8 * half;
                if (gr < E) {
                    int c1 = col1[gr];
                    bool emit = final_mode ? true : (col0[gr] != c1);
                    #pragma unroll
                    for (int n = 0; n < 8; n++) {
                        int cc = wn * 64 + 8 * n + 2 * tx4;
                        float2 bb = *(const float2*)&b2[cc];
                        float2 o;
                        o.x = acc[m][n][2 * half + 0] + bb.x;
                        o.y = acc[m][n][2 * half + 1] + bb.y;
                        if (!final_mode) {
                            *(float2*)&g_lgX[(size_t)gr * DD + cc] = o;
                            if (emit) {
                                float2 xs = *(const float2*)&x[(size_t)c1 * DD + cc];
                                float2 v;
                                v.x = fmaxf(o.x + xs.x, 0.f);
                                v.y = fmaxf(o.y + xs.y, 0.f);
                                red_add_v2(&Sout[(size_t)c1 * DD + cc], v);
                            }
                        } else {
                            red_add_v2(&Sout[(size_t)c1 * DD + cc], o);
                        }
                    }
                }
            }
        }
        BAR(barid);   // protect sA (T) from next tile's staging
    }
}

// ----------------------- out = x + relu(Sf/cnt or 0) ------------------------
__global__ void k_fout(const float* __restrict__ x, float* __restrict__ out, int N)
{
    int idx = blockIdx.x * blockDim.x + threadIdx.x;
    int v = idx >> 5, q = idx & 31;
    if (v >= N) return;
    float c   = g_cnt[v];
    float inv = (c > 0.f) ? (1.f / c) : 0.f;
    float4 s  = ((const float4*)g_Sf)[(size_t)v * DV + q];
    float4 xv = ((const float4*)x)[(size_t)v * DV + q];
    float4 o;
    o.x = xv.x + fmaxf(s.x * inv, 0.f);
    o.y = xv.y + fmaxf(s.y * inv, 0.f);
    o.z = xv.z + fmaxf(s.z * inv, 0.f);
    o.w = xv.w + fmaxf(s.w * inv, 0.f);
    ((float4*)out)[(size_t)v * DV + q] = o;
}

// ---------------------------------------------------------------------------
extern "C" void kernel_launch(void* const* d_in, const int* in_sizes, int n_in,
                              void* d_out, int out_size)
{
    const float* x    = (const float*)d_in[0];
    const float* W1   = (const float*)d_in[1];
    const float* b1   = (const float*)d_in[2];
    const float* W2   = (const float*)d_in[3];
    const float* b2   = (const float*)d_in[4];
    const int*   col0 = (const int*)d_in[5];
    const int*   col1 = (const int*)d_in[6];
    // lg_src / lg_dst / edge_attr_idx are algebraically redundant.

    const int E = in_sizes[5];
    const int N = in_sizes[0] / DD;
    float* out = (float*)d_out;

    void *pS0, *pS1, *pSf, *pC;
    cudaGetSymbolAddress(&pS0, g_S0);
    cudaGetSymbolAddress(&pS1, g_S1);
    cudaGetSymbolAddress(&pSf, g_Sf);
    cudaGetSymbolAddress(&pC,  g_cnt);

    cudaFuncSetAttribute((const void*)k_mlp,
                         cudaFuncAttributeMaxDynamicSharedMemorySize, SMEM_BYTES);

    int smcount = 148;
    cudaDeviceGetAttribute(&smcount, cudaDevAttrMultiProcessorCount, 0);

    const int tpb = 256;
    const int nbE = (E * 32 + tpb - 1) / tpb;
    const int nbN = (N * 32 + tpb - 1) / tpb;
    const int ntiles  = (E + TILE - 1) / TILE;
    const int tstride = 2 * smcount;

    k_zero<<<(N * 32 + tpb - 1) / tpb, tpb>>>((float4*)pS0, (float4*)pS1,
                                              (float4*)pSf, (float*)pC,
                                              N * 32, N);
    k_wt<<<(DD * DD + tpb - 1) / tpb, tpb>>>(W1, W2);
    k_init<<<nbE, tpb>>>(x, col0, col1, E);
    k_mlp<<<smcount, tpb, SMEM_BYTES>>>(col0, col1, x, b1, b2,
                                        (const float*)pS0, (float*)pS1,
                                        E, 0, ntiles, tstride);
    k_mlp<<<smcount, tpb, SMEM_BYTES>>>(col0, col1, x, b1, b2,
                                        (const float*)pS1, (float*)pSf,
                                        E, 1, ntiles, tstride);
    k_fout<<<nbN, tpb>>>(x, out, N);
}

// round 5
// speedup vs baseline: 1.9154x; 1.1745x over previous
#include <cuda_runtime.h>
#include <cstdint>

// ---------------------------------------------------------------------------
// LGNN GINE layer, algebraically collapsed + linearity-split tf32 MMA MLP.
//   lgX  = 0.5*(x[col0]+x[col1])                          (stored tf32-rounded)
//   2x:  S[v]  = sum_{i: col1[i]==v, col0[i]!=col1[i]} relu(lgX[i]+x[v])
//        SW1   = tf32(S) @ W1                             (separate small GEMM)
//        lgX   = relu(lgX@W1 + SW1[col0] + b1) @ W2 + b2
//   out  = x + relu( segment_mean(lgX, col1) )
// k_mlp: persistent, 8 warps = 4 independent pairs, 32-row tiles, cp.async
// A staging, SW1 gather in epilogue-1, message scatter fused in epilogue-2.
// ---------------------------------------------------------------------------

#define DD   128
#define DV   32
#define MAXE 200000
#define MAXN 50000
#define TILE 32

__device__ float g_S0[(size_t)MAXN * DD];
__device__ float g_S1[(size_t)MAXN * DD];
__device__ float g_Sf[(size_t)MAXN * DD];
__device__ float g_SW1[(size_t)MAXN * DD];
__device__ float g_lgX[(size_t)MAXE * DD];
__device__ float g_cnt[MAXN];
__device__ float g_Wr1[DD * DD];   // W1 tf32-rounded, [k][n]
__device__ float g_Wr2[DD * DD];

// ----------------------------- helpers --------------------------------------
__device__ __forceinline__ uint32_t smem_u32(const void* p) {
    uint32_t a;
    asm("{ .reg .u64 t; cvta.to.shared.u64 t, %1; cvt.u32.u64 %0, t; }"
        : "=r"(a) : "l"(p));
    return a;
}
__device__ __forceinline__ float tf32r(float f) {
    uint32_t u;
    asm("cvt.rna.tf32.f32 %0, %1;" : "=r"(u) : "f"(f));
    return __uint_as_float(u);
}
__device__ __forceinline__ void red_add_v4(float* p, float4 v) {
    asm volatile("red.global.add.v4.f32 [%0], {%1,%2,%3,%4};"
                 :: "l"(p), "f"(v.x), "f"(v.y), "f"(v.z), "f"(v.w) : "memory");
}
__device__ __forceinline__ void red_add_v2(float* p, float2 v) {
    asm volatile("red.global.add.v2.f32 [%0], {%1,%2};"
                 :: "l"(p), "f"(v.x), "f"(v.y) : "memory");
}
__device__ __forceinline__ void mma_tf32(float* d, const uint32_t* a,
                                         const uint32_t* b) {
    asm volatile(
        "mma.sync.aligned.m16n8k8.row.col.f32.tf32.tf32.f32 "
        "{%0,%1,%2,%3}, {%4,%5,%6,%7}, {%8,%9}, {%0,%1,%2,%3};"
        : "+f"(d[0]), "+f"(d[1]), "+f"(d[2]), "+f"(d[3])
        : "r"(a[0]), "r"(a[1]), "r"(a[2]), "r"(a[3]), "r"(b[0]), "r"(b[1]));
}
__device__ __forceinline__ void cp_async16(uint32_t dst, const void* src) {
    asm volatile("cp.async.cg.shared.global [%0], [%1], 16;"
                 :: "r"(dst), "l"(src) : "memory");
}
#define CP_COMMIT() asm volatile("cp.async.commit_group;" ::: "memory")
#define CP_WAIT0()  asm volatile("cp.async.wait_group 0;"  ::: "memory")
#define BAR(id)     asm volatile("bar.sync %0, 64;" :: "r"(id) : "memory")

#define LDA 132
#define LDW 136

// GEMM fragment body: acc[2][8][4] += A(rows R0.., k) * W(k, wn*64..)
#define GEMM_BODY(UW, UA, R0)                                                  \
    _Pragma("unroll")                                                          \
    for (int kk = 0; kk < 16; kk++) {                                          \
        uint32_t a[2][4], b[8][2];                                             \
        _Pragma("unroll")                                                      \
        for (int m = 0; m < 2; m++) {                                          \
            int rb = (R0) + 16 * m;                                            \
            a[m][0] = (UA)[(rb + ty) * LDA + kk * 8 + tx4];                    \
            a[m][1] = (UA)[(rb + ty + 8) * LDA + kk * 8 + tx4];                \
            a[m][2] = (UA)[(rb + ty) * LDA + kk * 8 + tx4 + 4];                \
            a[m][3] = (UA)[(rb + ty + 8) * LDA + kk * 8 + tx4 + 4];            \
        }                                                                      \
        _Pragma("unroll")                                                      \
        for (int n = 0; n < 8; n++) {                                          \
            int cc = wn * 64 + 8 * n + ty;                                     \
            b[n][0] = (UW)[(kk * 8 + tx4) * LDW + cc];                         \
            b[n][1] = (UW)[(kk * 8 + tx4 + 4) * LDW + cc];                     \
        }                                                                      \
        _Pragma("unroll")                                                      \
        for (int m = 0; m < 2; m++)                                            \
            _Pragma("unroll")                                                  \
            for (int n = 0; n < 8; n++)                                        \
                mma_tf32(acc[m][n], a[m], b[n]);                               \
    }

// ------------------- zero scratch + weight rounding --------------------------
__global__ void k_zero(float4* s0, float4* s1, float4* sf, float* cnt,
                       int n4, int n)
{
    int i = blockIdx.x * blockDim.x + threadIdx.x;
    float4 z = make_float4(0.f, 0.f, 0.f, 0.f);
    if (i < n4) { s0[i] = z; s1[i] = z; sf[i] = z; }
    if (i < n)  cnt[i] = 0.f;
}
__global__ void k_wt(const float* __restrict__ W1, const float* __restrict__ W2)
{
    int t = blockIdx.x * blockDim.x + threadIdx.x;
    if (t >= DD * DD) return;
    g_Wr1[t] = tf32r(W1[t]);
    g_Wr2[t] = tf32r(W2[t]);
}

// ---- init: lgX = tf32r(0.5*(x[c0]+x[c1])); scatter relu -> S0; cnt ---------
__global__ void k_init(const float* __restrict__ x,
                       const int* __restrict__ col0,
                       const int* __restrict__ col1, int E)
{
    int idx = blockIdx.x * blockDim.x + threadIdx.x;
    int e = idx >> 5, q = idx & 31;
    if (e >= E) return;
    int c0 = col0[e], c1 = col1[e];
    const float4* x4 = (const float4*)x;
    float4 a = x4[(size_t)c0 * DV + q];
    float4 b = x4[(size_t)c1 * DV + q];
    float4 r;
    r.x = 0.5f * (a.x + b.x);
    r.y = 0.5f * (a.y + b.y);
    r.z = 0.5f * (a.z + b.z);
    r.w = 0.5f * (a.w + b.w);
    if (c0 != c1) {
        float4 v;
        v.x = fmaxf(r.x + b.x, 0.f);
        v.y = fmaxf(r.y + b.y, 0.f);
        v.z = fmaxf(r.z + b.z, 0.f);
        v.w = fmaxf(r.w + b.w, 0.f);
        red_add_v4(&g_S0[(size_t)c1 * DD + 4 * q], v);
    }
    float4 rr;
    rr.x = tf32r(r.x); rr.y = tf32r(r.y); rr.z = tf32r(r.z); rr.w = tf32r(r.w);
    ((float4*)g_lgX)[(size_t)e * DV + q] = rr;
    if (q == 0) atomicAdd(&g_cnt[c1], 1.0f);
}

// ------------------- k_sw1: SW1 = tf32(S) @ W1 (N rows) ---------------------
#define SW1_SMEM ((128 * LDW + 128 * LDA) * 4)
__global__ void __launch_bounds__(256, 1)
k_sw1(const float* __restrict__ Sin, int N)
{
    extern __shared__ float sm[];
    float* sW = sm;                  // [128][LDW]
    float* sA = sm + 128 * LDW;      // [128][LDA]

    const int tid  = threadIdx.x;
    const int wid  = tid >> 5, lane = tid & 31;
    const int wm   = wid >> 1, wn = wid & 1;
    const int ty   = lane >> 2, tx4 = lane & 3;
    const int R0   = wm * 32;
    const int row0 = blockIdx.x * 128;

    #pragma unroll
    for (int i = tid; i < 4096; i += 256) {
        int k = i >> 5, n4 = i & 31;
        *(float4*)&sW[k * LDW + 4 * n4] = ((const float4*)g_Wr1)[i];
    }
    #pragma unroll
    for (int i = tid; i < 4096; i += 256) {
        int r = i >> 5, q = i & 31;
        int gr = row0 + r;
        float4 v = make_float4(0.f, 0.f, 0.f, 0.f);
        if (gr < N) {
            float4 s = ((const float4*)Sin)[(size_t)gr * DV + q];
            v.x = tf32r(s.x); v.y = tf32r(s.y);
            v.z = tf32r(s.z); v.w = tf32r(s.w);
        }
        *(float4*)&sA[r * LDA + 4 * q] = v;
    }
    __syncthreads();

    float acc[2][8][4];
    #pragma unroll
    for (int m = 0; m < 2; m++)
        #pragma unroll
        for (int n = 0; n < 8; n++)
            #pragma unroll
            for (int j = 0; j < 4; j++) acc[m][n][j] = 0.f;

    const uint32_t* uA = (const uint32_t*)sA;
    const uint32_t* uW = (const uint32_t*)sW;
    GEMM_BODY(uW, uA, R0);

    #pragma unroll
    for (int m = 0; m < 2; m++)
        #pragma unroll
        for (int half = 0; half < 2; half++) {
            int gr = row0 + R0 + 16 * m + ty + 8 * half;
            if (gr >= N) continue;
            #pragma unroll
            for (int n = 0; n < 8; n++) {
                int cc = wn * 64 + 8 * n + 2 * tx4;
                float2 o;
                o.x = acc[m][n][2 * half + 0];
                o.y = acc[m][n][2 * half + 1];
                *(float2*)&g_SW1[(size_t)gr * DD + cc] = o;
            }
        }
}

// ----------------- persistent fused MLP + message scatter -------------------
#define SW_WORDS (128 * LDW)
#define SA_WORDS (TILE * LDA)
#define SMEM_BYTES ((2 * SW_WORDS + 4 * SA_WORDS) * 4)   // 206848 B

__global__ void __launch_bounds__(256, 1)
k_mlp(const int* __restrict__ col0, const int* __restrict__ col1,
      const float* __restrict__ x,
      const float* __restrict__ b1, const float* __restrict__ b2,
      float* __restrict__ Sout,
      int E, int final_mode, int ntiles, int tstride)
{
    extern __shared__ float sm[];
    float* sW1 = sm;
    float* sW2 = sm + SW_WORDS;

    const int tid  = threadIdx.x;
    const int wid  = tid >> 5, lane = tid & 31;
    const int pid  = wid >> 1;                 // pair 0..3
    const int wn   = wid & 1;                  // column half within pair
    const int ty   = lane >> 2, tx4 = lane & 3;
    const int barid = 1 + pid;

    float* sA = sm + 2 * SW_WORDS + pid * SA_WORDS;
    const uint32_t* uA  = (const uint32_t*)sA;
    const uint32_t* uW1 = (const uint32_t*)sW1;
    const uint32_t* uW2 = (const uint32_t*)sW2;
    const uint32_t sAu = smem_u32(sA);

    // staging role within the pair: 64 threads = 32 rows x 2 half-rows
    const int t64   = wn * 32 + lane;
    const int srow  = t64 >> 1;            // 0..31
    const int wpart = (t64 & 1) * 16;      // float4 group 0..15 / 16..31

    // stage weights once
    #pragma unroll
    for (int i = tid; i < 4096; i += 256) {
        int k = i >> 5, n4 = i & 31;
        *(float4*)&sW1[k * LDW + 4 * n4] = ((const float4*)g_Wr1)[i];
        *(float4*)&sW2[k * LDW + 4 * n4] = ((const float4*)g_Wr2)[i];
    }
    __syncthreads();

    int tile = blockIdx.x * 4 + pid;

    // prologue: stage first tile
    if (tile < ntiles) {
        int gr = tile * TILE + srow;
        if (gr < E) {
            const float* src = &g_lgX[(size_t)gr * DD + 4 * wpart];
            uint32_t dst = sAu + (srow * LDA + 4 * wpart) * 4;
            #pragma unroll
            for (int j = 0; j < 16; j++)
                cp_async16(dst + 16 * j, src + 4 * j);
        } else {
            float4 z = make_float4(0.f, 0.f, 0.f, 0.f);
            #pragma unroll
            for (int j = 0; j < 16; j++)
                *(float4*)&sA[srow * LDA + 4 * (wpart + j)] = z;
        }
        CP_COMMIT();
    }

    for (; tile < ntiles; tile += tstride) {
        const int row0 = tile * TILE;
        CP_WAIT0();
        BAR(barid);

        float acc[2][8][4];
        #pragma unroll
        for (int m = 0; m < 2; m++)
            #pragma unroll
            for (int n = 0; n < 8; n++)
                #pragma unroll
                for (int j = 0; j < 4; j++) acc[m][n][j] = 0.f;

        // ---------------- GEMM 1: acc = lgX @ W1 ----------------
        GEMM_BODY(uW1, uA, 0);
        BAR(barid);

        // epilogue 1: T = tf32r(relu(acc + SW1[col0[r]] + b1)) -> sA in place
        #pragma unroll
        for (int m = 0; m < 2; m++) {
            int gr0 = row0 + 16 * m + ty;
            int gr1 = gr0 + 8;
            int c00 = (gr0 < E) ? col0[gr0] : 0;
            int c01 = (gr1 < E) ? col0[gr1] : 0;
            const float* sw0 = &g_SW1[(size_t)c00 * DD];
            const float* sw1 = &g_SW1[(size_t)c01 * DD];
            int rb = 16 * m + ty;
            #pragma unroll
            for (int n = 0; n < 8; n++) {
                int cc = wn * 64 + 8 * n + 2 * tx4;
                float2 bb = *(const float2*)&b1[cc];
                float2 s0 = *(const float2*)&sw0[cc];
                float2 s1 = *(const float2*)&sw1[cc];
                float2 t0, t1;
                t0.x = tf32r(fmaxf(acc[m][n][0] + s0.x + bb.x, 0.f));
                t0.y = tf32r(fmaxf(acc[m][n][1] + s0.y + bb.y, 0.f));
                t1.x = tf32r(fmaxf(acc[m][n][2] + s1.x + bb.x, 0.f));
                t1.y = tf32r(fmaxf(acc[m][n][3] + s1.y + bb.y, 0.f));
                *(float2*)&sA[rb * LDA + cc]       = t0;
                *(float2*)&sA[(rb + 8) * LDA + cc] = t1;
                acc[m][n][0] = 0.f; acc[m][n][1] = 0.f;
                acc[m][n][2] = 0.f; acc[m][n][3] = 0.f;
            }
        }
        BAR(barid);

        // ---------------- GEMM 2: acc = T @ W2 ----------------
        GEMM_BODY(uW2, uA, 0);
        BAR(barid);   // GEMM2 reads done -> buffer free for next tile

        // stage next tile (overlaps epilogue 2)
        {
            int nt = tile + tstride;
            if (nt < ntiles) {
                int gr = nt * TILE + srow;
                if (gr < E) {
                    const float* src = &g_lgX[(size_t)gr * DD + 4 * wpart];
                    uint32_t dst = sAu + (srow * LDA + 4 * wpart) * 4;
                    #pragma unroll
                    for (int j = 0; j < 16; j++)
                        cp_async16(dst + 16 * j, src + 4 * j);
                } else {
                    float4 z = make_float4(0.f, 0.f, 0.f, 0.f);
                    #pragma unroll
                    for (int j = 0; j < 16; j++)
                        *(float4*)&sA[srow * LDA + 4 * (wpart + j)] = z;
                }
                CP_COMMIT();
            }
        }

        // epilogue 2: O = acc + b2 ; write lgX tf32 (unless final); scatter
        #pragma unroll
        for (int m = 0; m < 2; m++) {
            #pragma unroll
            for (int half = 0; half < 2; half++) {
                int gr = row0 + 16 * m + ty + 8 * half;
                if (gr >= E) continue;
                int c1 = col1[gr];
                bool emit = final_mode ? true : (col0[gr] != c1);
                #pragma unroll
                for (int n = 0; n < 8; n++) {
                    int cc = wn * 64 + 8 * n + 2 * tx4;
                    float2 bb = *(const float2*)&b2[cc];
                    float2 o;
                    o.x = acc[m][n][2 * half + 0] + bb.x;
                    o.y = acc[m][n][2 * half + 1] + bb.y;
                    if (!final_mode) {
                        float2 rr;
                        rr.x = tf32r(o.x); rr.y = tf32r(o.y);
                        *(float2*)&g_lgX[(size_t)gr * DD + cc] = rr;
                        if (emit) {
                            float2 xs = *(const float2*)&x[(size_t)c1 * DD + cc];
                            float2 v;
                            v.x = fmaxf(o.x + xs.x, 0.f);
                            v.y = fmaxf(o.y + xs.y, 0.f);
                            red_add_v2(&Sout[(size_t)c1 * DD + cc], v);
                        }
                    } else {
                        red_add_v2(&Sout[(size_t)c1 * DD + cc], o);
                    }
                }
            }
        }
    }
}

// ----------------------- out = x + relu(Sf/cnt or 0) ------------------------
__global__ void k_fout(const float* __restrict__ x, float* __restrict__ out, int N)
{
    int idx = blockIdx.x * blockDim.x + threadIdx.x;
    int v = idx >> 5, q = idx & 31;
    if (v >= N) return;
    float c   = g_cnt[v];
    float inv = (c > 0.f) ? (1.f / c) : 0.f;
    float4 s  = ((const float4*)g_Sf)[(size_t)v * DV + q];
    float4 xv = ((const float4*)x)[(size_t)v * DV + q];
    float4 o;
    o.x = xv.x + fmaxf(s.x * inv, 0.f);
    o.y = xv.y + fmaxf(s.y * inv, 0.f);
    o.z = xv.z + fmaxf(s.z * inv, 0.f);
    o.w = xv.w + fmaxf(s.w * inv, 0.f);
    ((float4*)out)[(size_t)v * DV + q] = o;
}

// ---------------------------------------------------------------------------
extern "C" void kernel_launch(void* const* d_in, const int* in_sizes, int n_in,
                              void* d_out, int out_size)
{
    const float* x    = (const float*)d_in[0];
    const float* W1   = (const float*)d_in[1];
    const float* b1   = (const float*)d_in[2];
    const float* W2   = (const float*)d_in[3];
    const float* b2   = (const float*)d_in[4];
    const int*   col0 = (const int*)d_in[5];
    const int*   col1 = (const int*)d_in[6];
    // lg_src / lg_dst / edge_attr_idx are algebraically redundant.

    const int E = in_sizes[5];
    const int N = in_sizes[0] / DD;
    float* out = (float*)d_out;

    void *pS0, *pS1, *pSf, *pC;
    cudaGetSymbolAddress(&pS0, g_S0);
    cudaGetSymbolAddress(&pS1, g_S1);
    cudaGetSymbolAddress(&pSf, g_Sf);
    cudaGetSymbolAddress(&pC,  g_cnt);

    cudaFuncSetAttribute((const void*)k_mlp,
                         cudaFuncAttributeMaxDynamicSharedMemorySize, SMEM_BYTES);
    cudaFuncSetAttribute((const void*)k_sw1,
                         cudaFuncAttributeMaxDynamicSharedMemorySize, SW1_SMEM);

    int smcount = 148;
    cudaDeviceGetAttribute(&smcount, cudaDevAttrMultiProcessorCount, 0);

    const int tpb = 256;
    const int nbE = (E * 32 + tpb - 1) / tpb;
    const int nbN = (N * 32 + tpb - 1) / tpb;
    const int nbS = (N + 127) / 128;
    const int ntiles  = (E + TILE - 1) / TILE;
    const int tstride = 4 * smcount;

    k_zero<<<(N * 32 + tpb - 1) / tpb, tpb>>>((float4*)pS0, (float4*)pS1,
                                              (float4*)pSf, (float*)pC,
                                              N * 32, N);
    k_wt<<<(DD * DD + tpb - 1) / tpb, tpb>>>(W1, W2);
    k_init<<<nbE, tpb>>>(x, col0, col1, E);

    k_sw1<<<nbS, tpb, SW1_SMEM>>>((const float*)pS0, N);
    k_mlp<<<smcount, tpb, SMEM_BYTES>>>(col0, col1, x, b1, b2,
                                        (float*)pS1, E, 0, ntiles, tstride);
    k_sw1<<<nbS, tpb, SW1_SMEM>>>((const float*)pS1, N);
    k_mlp<<<smcount, tpb, SMEM_BYTES>>>(col0, col1, x, b1, b2,
                                        (float*)pSf, E, 1, ntiles, tstride);
    k_fout<<<nbN, tpb>>>(x, out, N);
}